// round 1
// baseline (speedup 1.0000x reference)
#include <cuda_runtime.h>
#include <cstdint>
#include <math.h>

// Problem constants
#define S_PER_B 8192        // n*h tokens per batch
#define NROWS   16384       // 2 * 8192
#define DD      64          // head dim
#define ATTN_ELEMS 134217728LL  // 2*8192*8192
#define SCALE_F 0.125f      // 1/sqrt(64)

// Scratch (device globals; no allocation allowed)
__device__ __align__(128) float g_q[NROWS * DD];
__device__ __align__(128) float g_k[NROWS * DD];
__device__ __align__(128) float g_v[NROWS * DD];
__device__ __align__(128) float g_rsum[NROWS];
__device__ __align__(128) float g_ao[2048 * 512];   // attention output (pre-MLP)
__device__ __align__(128) float g_h[2048 * 1024];   // MLP hidden

__device__ __forceinline__ uint32_t fbits(float f) { return __float_as_uint(f); }
__device__ __forceinline__ uint32_t tf32r(float f) {
    uint32_t r; asm("cvt.rna.tf32.f32 %0, %1;" : "=r"(r) : "f"(f)); return r;
}
__device__ __forceinline__ float tf32f(float f) { return __uint_as_float(tf32r(f)); }

__device__ __forceinline__ void mma8(float c[4], const uint32_t a[4], const uint32_t b[2]) {
    asm volatile(
        "mma.sync.aligned.m16n8k8.row.col.f32.tf32.tf32.f32 "
        "{%0,%1,%2,%3},{%4,%5,%6,%7},{%8,%9},{%0,%1,%2,%3};"
        : "+f"(c[0]), "+f"(c[1]), "+f"(c[2]), "+f"(c[3])
        : "r"(a[0]), "r"(a[1]), "r"(a[2]), "r"(a[3]), "r"(b[0]), "r"(b[1]));
}

__device__ __forceinline__ float gelu_exact(float x) {
    return 0.5f * x * (1.0f + erff(x * 0.70710678118654752f));
}

// ---------------------------------------------------------------------------
// K1: QKV projection. x is [16384][64] (reshape of [2,1024,512] is layout-identical).
// q[s][e] = sum_d x[s][d] * wq[e][d]. Stores tf32-rounded values.
// ---------------------------------------------------------------------------
__global__ void __launch_bounds__(256) qkv_kernel(const float* __restrict__ x,
                                                  const float* __restrict__ wq,
                                                  const float* __restrict__ wk,
                                                  const float* __restrict__ wv) {
    __shared__ float swq[4096], swk[4096], swv[4096];  // transposed: [d][e]
    __shared__ float sx[4][64];
    int tid = threadIdx.x;
    for (int i = tid; i < 4096; i += 256) {
        int e = i >> 6, d = i & 63;
        swq[d * 64 + e] = wq[i]; swk[d * 64 + e] = wk[i]; swv[d * 64 + e] = wv[i];
    }
    int e = tid & 63, sub = tid >> 6;
    int base = blockIdx.x * 32;
    for (int it = 0; it < 8; ++it) {
        int row = base + it * 4 + sub;
        __syncthreads();
        sx[sub][e] = x[row * 64 + e];
        __syncthreads();
        float aq = 0.f, ak = 0.f, av = 0.f;
#pragma unroll
        for (int d = 0; d < 64; ++d) {
            float xv = sx[sub][d];
            aq = fmaf(xv, swq[d * 64 + e], aq);
            ak = fmaf(xv, swk[d * 64 + e], ak);
            av = fmaf(xv, swv[d * 64 + e], av);
        }
        g_q[row * 64 + e] = tf32f(aq);
        g_k[row * 64 + e] = tf32f(ak);
        g_v[row * 64 + e] = tf32f(av);
    }
}

// ---------------------------------------------------------------------------
// Pass 1: row sums of exp(scores). CTA = (b, 128-row block), loops over all K tiles.
// grid = 128 CTAs, 256 threads (8 warps, 4m x 2n layout over the 128x128 tile).
// ---------------------------------------------------------------------------
#define TS 68  // smem row stride (floats) for 64-wide tiles

__global__ void __launch_bounds__(256) rowsum_kernel() {
    extern __shared__ float sm1[];
    float* Qs = sm1;                 // [128][68]
    float* Ks = sm1 + 128 * TS;      // [128][68]
    float* red = sm1 + 2 * 128 * TS; // [128][2]
    int b = blockIdx.x >> 6, rb = blockIdx.x & 63;
    int tid = threadIdx.x, warp = tid >> 5, lane = tid & 31;
    int g = lane >> 2, tg = lane & 3, wm = warp >> 1, wn = warp & 1;
    int s0 = b * S_PER_B + rb * 128;

    const float* Qg = g_q + (long)s0 * DD;
    for (int i = tid; i < 2048; i += 256) {
        int r = i >> 4, c = (i & 15) << 2;
        float4 v = *(const float4*)(Qg + r * DD + c);
        float* d = Qs + r * TS + c;
        d[0] = v.x; d[1] = v.y; d[2] = v.z; d[3] = v.w;
    }

    float rs[4] = {0.f, 0.f, 0.f, 0.f};
    for (int tj = 0; tj < 64; ++tj) {
        __syncthreads();
        const float* Kg = g_k + (long)(b * S_PER_B + tj * 128) * DD;
        for (int i = tid; i < 2048; i += 256) {
            int r = i >> 4, c = (i & 15) << 2;
            float4 v = *(const float4*)(Kg + r * DD + c);
            float* d = Ks + r * TS + c;
            d[0] = v.x; d[1] = v.y; d[2] = v.z; d[3] = v.w;
        }
        __syncthreads();

        float s[2][8][4];
#pragma unroll
        for (int mi = 0; mi < 2; ++mi)
#pragma unroll
            for (int ni = 0; ni < 8; ++ni)
#pragma unroll
                for (int q = 0; q < 4; ++q) s[mi][ni][q] = 0.f;

#pragma unroll
        for (int k = 0; k < 8; ++k) {
            uint32_t a[2][4];
#pragma unroll
            for (int mi = 0; mi < 2; ++mi) {
                const float* p = Qs + (32 * wm + 16 * mi + g) * TS + 8 * k + tg;
                a[mi][0] = fbits(p[0]); a[mi][1] = fbits(p[8 * TS]);
                a[mi][2] = fbits(p[4]); a[mi][3] = fbits(p[8 * TS + 4]);
            }
#pragma unroll
            for (int ni = 0; ni < 8; ++ni) {
                const float* p = Ks + (64 * wn + 8 * ni + g) * TS + 8 * k + tg;
                uint32_t bb[2]; bb[0] = fbits(p[0]); bb[1] = fbits(p[4]);
                mma8(s[0][ni], a[0], bb);
                mma8(s[1][ni], a[1], bb);
            }
        }
#pragma unroll
        for (int mi = 0; mi < 2; ++mi)
#pragma unroll
            for (int ni = 0; ni < 8; ++ni) {
                rs[2 * mi]     += __expf(s[mi][ni][0] * SCALE_F) + __expf(s[mi][ni][1] * SCALE_F);
                rs[2 * mi + 1] += __expf(s[mi][ni][2] * SCALE_F) + __expf(s[mi][ni][3] * SCALE_F);
            }
    }
#pragma unroll
    for (int j = 0; j < 4; ++j) {
        rs[j] += __shfl_xor_sync(0xffffffffu, rs[j], 1);
        rs[j] += __shfl_xor_sync(0xffffffffu, rs[j], 2);
    }
    __syncthreads();
    if (tg == 0) {
#pragma unroll
        for (int j = 0; j < 4; ++j) {
            int r = 32 * wm + 16 * (j >> 1) + 8 * (j & 1) + g;
            red[r * 2 + wn] = rs[j];
        }
    }
    __syncthreads();
    if (tid < 128) g_rsum[s0 + tid] = red[tid * 2] + red[tid * 2 + 1];
}

// ---------------------------------------------------------------------------
// Pass 2: recompute scores, normalize via precomputed row sums, write attn (536MB),
// and fuse P@V accumulation. CTA = (b, 128-row block), loops over all 64 K/V tiles.
// ---------------------------------------------------------------------------
#define VS 72    // V smem stride
#define PS 132   // P stage stride

__global__ void __launch_bounds__(256) attn_pv_kernel(float* __restrict__ attn) {
    extern __shared__ float sm2[];
    float* Qs  = sm2;                              // 128*68
    float* Ks  = Qs + 128 * TS;                    // 128*68
    float* Vs  = Ks + 128 * TS;                    // 128*72
    float* Pst = Vs + 128 * VS;                    // 128*132
    int b = blockIdx.x >> 6, rb = blockIdx.x & 63;
    int tid = threadIdx.x, warp = tid >> 5, lane = tid & 31;
    int g = lane >> 2, tg = lane & 3, wm = warp >> 1, wn = warp & 1;
    int s0 = b * S_PER_B + rb * 128;

    const float* Qg = g_q + (long)s0 * DD;
    for (int i = tid; i < 2048; i += 256) {
        int r = i >> 4, c = (i & 15) << 2;
        float4 v = *(const float4*)(Qg + r * DD + c);
        float* d = Qs + r * TS + c;
        d[0] = v.x; d[1] = v.y; d[2] = v.z; d[3] = v.w;
    }

    float inv[4];
#pragma unroll
    for (int j = 0; j < 4; ++j) {
        int r = 32 * wm + 16 * (j >> 1) + 8 * (j & 1) + g;
        inv[j] = 1.0f / g_rsum[s0 + r];
    }

    float pv[2][4][4];
#pragma unroll
    for (int mi = 0; mi < 2; ++mi)
#pragma unroll
        for (int ni = 0; ni < 4; ++ni)
#pragma unroll
            for (int q = 0; q < 4; ++q) pv[mi][ni][q] = 0.f;

    float* attn_base = attn + (long)b * S_PER_B * S_PER_B + (long)(rb * 128) * S_PER_B;

    for (int tj = 0; tj < 64; ++tj) {
        __syncthreads();
        const float* Kg = g_k + (long)(b * S_PER_B + tj * 128) * DD;
        const float* Vg = g_v + (long)(b * S_PER_B + tj * 128) * DD;
        for (int i = tid; i < 2048; i += 256) {
            int r = i >> 4, c = (i & 15) << 2;
            float4 v = *(const float4*)(Kg + r * DD + c);
            float* d = Ks + r * TS + c;
            d[0] = v.x; d[1] = v.y; d[2] = v.z; d[3] = v.w;
            float4 w = *(const float4*)(Vg + r * DD + c);
            float* e = Vs + r * VS + c;
            e[0] = w.x; e[1] = w.y; e[2] = w.z; e[3] = w.w;
        }
        __syncthreads();

        // scores mma: warp tile 32x64 (same ordering as pass 1 -> bitwise-identical acc)
        float s[2][8][4];
#pragma unroll
        for (int mi = 0; mi < 2; ++mi)
#pragma unroll
            for (int ni = 0; ni < 8; ++ni)
#pragma unroll
                for (int q = 0; q < 4; ++q) s[mi][ni][q] = 0.f;

#pragma unroll
        for (int k = 0; k < 8; ++k) {
            uint32_t a[2][4];
#pragma unroll
            for (int mi = 0; mi < 2; ++mi) {
                const float* p = Qs + (32 * wm + 16 * mi + g) * TS + 8 * k + tg;
                a[mi][0] = fbits(p[0]); a[mi][1] = fbits(p[8 * TS]);
                a[mi][2] = fbits(p[4]); a[mi][3] = fbits(p[8 * TS + 4]);
            }
#pragma unroll
            for (int ni = 0; ni < 8; ++ni) {
                const float* p = Ks + (64 * wn + 8 * ni + g) * TS + 8 * k + tg;
                uint32_t bb[2]; bb[0] = fbits(p[0]); bb[1] = fbits(p[4]);
                mma8(s[0][ni], a[0], bb);
                mma8(s[1][ni], a[1], bb);
            }
        }

        // exp + normalize, stage normalized attn tile into smem (fp32)
#pragma unroll
        for (int mi = 0; mi < 2; ++mi)
#pragma unroll
            for (int ni = 0; ni < 8; ++ni) {
                float p0 = __expf(s[mi][ni][0] * SCALE_F) * inv[2 * mi];
                float p1 = __expf(s[mi][ni][1] * SCALE_F) * inv[2 * mi];
                float p2 = __expf(s[mi][ni][2] * SCALE_F) * inv[2 * mi + 1];
                float p3 = __expf(s[mi][ni][3] * SCALE_F) * inv[2 * mi + 1];
                int r = 32 * wm + 16 * mi + g;
                int c = 64 * wn + 8 * ni + 2 * tg;
                Pst[r * PS + c] = p0;
                Pst[r * PS + c + 1] = p1;
                Pst[(r + 8) * PS + c] = p2;
                Pst[(r + 8) * PS + c + 1] = p3;
            }
        __syncthreads();

        // write attn tile to gmem (coalesced float4 rows)
        float* dst = attn_base + tj * 128;
        for (int i = tid; i < 4096; i += 256) {
            int r = i >> 5, c = (i & 31) << 2;
            float4 v = *(float4*)(Pst + r * PS + c);
            *(float4*)(dst + (long)r * S_PER_B + c) = v;
        }

        // P@V mma: out tile 128x64 per CTA, warp tile 32x32; k = 128 (16 steps)
#pragma unroll
        for (int k = 0; k < 16; ++k) {
            uint32_t a[2][4];
#pragma unroll
            for (int mi = 0; mi < 2; ++mi) {
                const float* p = Pst + (32 * wm + 16 * mi + g) * PS + 8 * k + tg;
                a[mi][0] = tf32r(p[0]); a[mi][1] = tf32r(p[8 * PS]);
                a[mi][2] = tf32r(p[4]); a[mi][3] = tf32r(p[8 * PS + 4]);
            }
#pragma unroll
            for (int ni = 0; ni < 4; ++ni) {
                const float* p = Vs + (8 * k + tg) * VS + 32 * wn + 8 * ni + g;
                uint32_t bb[2]; bb[0] = fbits(p[0]); bb[1] = fbits(p[4 * VS]);
                mma8(pv[0][ni], a[0], bb);
                mma8(pv[1][ni], a[1], bb);
            }
        }
    }

    // write attention output (already normalized) to scratch
#pragma unroll
    for (int mi = 0; mi < 2; ++mi)
#pragma unroll
        for (int ni = 0; ni < 4; ++ni) {
            int r = 32 * wm + 16 * mi + g;
            int c = 32 * wn + 8 * ni + 2 * tg;
            long row = (long)s0 + r;
            g_ao[row * DD + c]           = pv[mi][ni][0];
            g_ao[row * DD + c + 1]       = pv[mi][ni][1];
            g_ao[(row + 8) * DD + c]     = pv[mi][ni][2];
            g_ao[(row + 8) * DD + c + 1] = pv[mi][ni][3];
        }
}

// ---------------------------------------------------------------------------
// MLP: C[M,N] = act(A[M,K] @ B[N,K]^T + bias). 64x64 tiles, tf32 mma.
// ---------------------------------------------------------------------------
template <int K, int N, int ACT>
__device__ __forceinline__ void mlp_body(const float* __restrict__ A,
                                         const float* __restrict__ B,
                                         const float* __restrict__ bias,
                                         float* __restrict__ C) {
    __shared__ float As[64 * TS], Bs[64 * TS];
    int tid = threadIdx.x, warp = tid >> 5, lane = tid & 31;
    int g = lane >> 2, tg = lane & 3, wm = warp >> 1, wn = warp & 1;
    int bm = blockIdx.x, bn = blockIdx.y;

    float acc[4][4];
#pragma unroll
    for (int ni = 0; ni < 4; ++ni)
#pragma unroll
        for (int q = 0; q < 4; ++q) acc[ni][q] = 0.f;

    const int nkt = K >> 6;
    for (int kt = 0; kt < nkt; ++kt) {
        __syncthreads();
        for (int i = tid; i < 1024; i += 256) {
            int r = i >> 4, c = (i & 15) << 2;
            float4 va = *(const float4*)(A + (long)(bm * 64 + r) * K + kt * 64 + c);
            As[r * TS + c] = tf32f(va.x); As[r * TS + c + 1] = tf32f(va.y);
            As[r * TS + c + 2] = tf32f(va.z); As[r * TS + c + 3] = tf32f(va.w);
            float4 vb = *(const float4*)(B + (long)(bn * 64 + r) * K + kt * 64 + c);
            Bs[r * TS + c] = tf32f(vb.x); Bs[r * TS + c + 1] = tf32f(vb.y);
            Bs[r * TS + c + 2] = tf32f(vb.z); Bs[r * TS + c + 3] = tf32f(vb.w);
        }
        __syncthreads();
#pragma unroll
        for (int k = 0; k < 8; ++k) {
            uint32_t a[4];
            const float* pa = As + (16 * wm + g) * TS + 8 * k + tg;
            a[0] = fbits(pa[0]); a[1] = fbits(pa[8 * TS]);
            a[2] = fbits(pa[4]); a[3] = fbits(pa[8 * TS + 4]);
#pragma unroll
            for (int ni = 0; ni < 4; ++ni) {
                const float* pb = Bs + (32 * wn + 8 * ni + g) * TS + 8 * k + tg;
                uint32_t bb[2]; bb[0] = fbits(pb[0]); bb[1] = fbits(pb[4]);
                mma8(acc[ni], a, bb);
            }
        }
    }
#pragma unroll
    for (int ni = 0; ni < 4; ++ni) {
        int col = bn * 64 + 32 * wn + 8 * ni + 2 * tg;
        int row0 = bm * 64 + 16 * wm + g;
        float bv0 = bias[col], bv1 = bias[col + 1];
        float v0 = acc[ni][0] + bv0, v1 = acc[ni][1] + bv1;
        float v2 = acc[ni][2] + bv0, v3 = acc[ni][3] + bv1;
        if (ACT) { v0 = gelu_exact(v0); v1 = gelu_exact(v1); v2 = gelu_exact(v2); v3 = gelu_exact(v3); }
        C[(long)row0 * N + col] = v0;
        C[(long)row0 * N + col + 1] = v1;
        C[(long)(row0 + 8) * N + col] = v2;
        C[(long)(row0 + 8) * N + col + 1] = v3;
    }
}

__global__ void __launch_bounds__(256) mlp1_kernel(const float* __restrict__ w1,
                                                   const float* __restrict__ b1) {
    mlp_body<512, 1024, 1>(g_ao, w1, b1, g_h);
}
__global__ void __launch_bounds__(256) mlp2_kernel(const float* __restrict__ w2,
                                                   const float* __restrict__ b2,
                                                   float* __restrict__ C) {
    mlp_body<1024, 512, 0>(g_h, w2, b2, C);
}

// ---------------------------------------------------------------------------
extern "C" void kernel_launch(void* const* d_in, const int* in_sizes, int n_in,
                              void* d_out, int out_size) {
    const float* x  = (const float*)d_in[0];
    const float* wq = (const float*)d_in[1];
    const float* wk = (const float*)d_in[2];
    const float* wv = (const float*)d_in[3];
    const float* w1 = (const float*)d_in[4];
    const float* b1 = (const float*)d_in[5];
    const float* w2 = (const float*)d_in[6];
    const float* b2 = (const float*)d_in[7];
    float* attn = (float*)d_out;
    float* y = attn + ATTN_ELEMS;

    const int smem1 = (2 * 128 * TS + 256) * 4;                       // 70,656 B
    const int smem2 = (2 * 128 * TS + 128 * VS + 128 * PS) * 4;       // 174,080 B
    cudaFuncSetAttribute(rowsum_kernel, cudaFuncAttributeMaxDynamicSharedMemorySize, smem1);
    cudaFuncSetAttribute(attn_pv_kernel, cudaFuncAttributeMaxDynamicSharedMemorySize, smem2);

    qkv_kernel<<<512, 256>>>(x, wq, wk, wv);
    rowsum_kernel<<<128, 256, smem1>>>();
    attn_pv_kernel<<<128, 256, smem2>>>(attn);
    mlp1_kernel<<<dim3(32, 16), 256>>>(w1, b1);
    mlp2_kernel<<<dim3(32, 8), 256>>>(w2, b2, y);
}